// round 7
// baseline (speedup 1.0000x reference)
#include <cuda_runtime.h>
#include <cuda_bf16.h>

// SupJSD (ContrastiveLossPlus) — class-owned-block sufficient-statistics formulation.
//
// loss = 0.01/D * sum_c (1/n_c) * [ entsum_c - sum_d seg[c][d]*log(max(seg[c][d]/n_c, EPS)) ]
//   seg[c][d]  = sum over rows i (of 3N) with label c of p_i[d],  p_i = x_i / max(||x_i||_2, 1e-12)
//   entsum_c   = sum over rows i with label c of sum_d p_i[d]*ln(p_i[d])
//   n_c        = count over the 3N concatenated rows (3x per-variant count)
// Per-row:  sum_d p ln p = inv*(S_xlogx + ln(inv)*S_x),  inv = 1/max(||x||,1e-12)
//
// Labels may arrive as int32 or int64 (JAX x64 ambiguity): a runtime sniff in
// zero_kernel sets g_lab64 (odd 32-bit words all zero -> int64), and the label
// fetch branches on it (warp-uniform; negligible cost).
//
// Grid: 80 classes x ceil(N/CHUNK) chunks. Each block ballot-compacts its
// chunk's matching rows into a queue, warps accumulate the class segment-sum
// in REGISTERS (no hot-path atomics), 6 independent LDG.128 per iteration
// (3 variants fused) -> DRAM-bound. One double-atomic flush per block.
// Anchor loop is pinned to unroll 1: at the 64-reg launch_bounds cap, an x2
// unroll would spill the float4 loads to local memory.

#define CLS   80
#define DIM   256
#define EPSF  1e-7
#define CHUNK 1024
#define NTHR  128   // 4 warps
#define NWRP  4
#define SUB   (CHUNK / NWRP)   // 256 labels scanned per warp

__device__ double g_seg[CLS * DIM];
__device__ double g_ent[CLS];
__device__ int    g_cnt[CLS];
__device__ int    g_lab64;

__global__ void zero_kernel(const int* labels_raw, int N) {
    int i = blockIdx.x * blockDim.x + threadIdx.x;
    if (i < CLS * DIM) g_seg[i] = 0.0;
    if (i < CLS) { g_ent[i] = 0.0; g_cnt[i] = 0; }
    if (blockIdx.x == 0 && threadIdx.x == 0) {
        // int64 LE labels in [0,80): every odd 32-bit word is 0.
        int nz = 0;
        int samples = (N < 256) ? N : 256;
        for (int k = 0; k < samples; k++) nz |= labels_raw[2 * k + 1];
        g_lab64 = (nz == 0) ? 1 : 0;
    }
}

__device__ __forceinline__ int load_label(const int* labels_raw, int i, int lab64) {
    return lab64 ? (int)((const long long*)labels_raw)[i] : labels_raw[i];
}

// Per-lane partial sums for one row fragment (8 values in two float4s).
__device__ __forceinline__ void lane_sums(const float4& x0, const float4& x1,
                                          float& s1, float& s2, float& sl)
{
    float va[8] = {x0.x, x0.y, x0.z, x0.w, x1.x, x1.y, x1.z, x1.w};
    s1 = 0.f; s2 = 0.f; sl = 0.f;
#pragma unroll
    for (int k = 0; k < 8; k++) {
        float x = va[k];
        s1 += x;
        s2 = fmaf(x, x, s2);
        sl += (x > 0.f) ? x * __logf(x) : 0.f;
    }
}

__device__ __forceinline__ float warp_red(float v) {
#pragma unroll
    for (int off = 16; off > 0; off >>= 1)
        v += __shfl_xor_sync(0xFFFFFFFFu, v, off);
    return v;
}

__device__ __forceinline__ void accum_row(const float4& x0, const float4& x1,
                                          float s1, float s2, float sl,
                                          float acc[8], double& entW)
{
    s1 = warp_red(s1);
    s2 = warp_red(s2);
    sl = warp_red(sl);
    float inv = 1.0f / fmaxf(sqrtf(s2), 1e-12f);
    entW += (double)(inv * (sl + __logf(inv) * s1));
    acc[0] = fmaf(x0.x, inv, acc[0]);
    acc[1] = fmaf(x0.y, inv, acc[1]);
    acc[2] = fmaf(x0.z, inv, acc[2]);
    acc[3] = fmaf(x0.w, inv, acc[3]);
    acc[4] = fmaf(x1.x, inv, acc[4]);
    acc[5] = fmaf(x1.y, inv, acc[5]);
    acc[6] = fmaf(x1.z, inv, acc[6]);
    acc[7] = fmaf(x1.w, inv, acc[7]);
}

extern "C" __global__ void __launch_bounds__(NTHR, 8)
main_kernel(const float* __restrict__ a, const float* __restrict__ b,
            const float* __restrict__ cc, const int* __restrict__ labels_raw,
            int N)
{
    __shared__ int    queue[CHUNK];      // per-warp segments of SUB entries
    __shared__ int    wcount[NWRP];
    __shared__ float  sred[NWRP * DIM];  // 4 KB
    __shared__ double sent[NWRP];
    __shared__ int    swcnt[NWRP];

    const int cls  = blockIdx.x % CLS;
    const int jchk = blockIdx.x / CLS;
    const int base = jchk * CHUNK;

    const int tid  = threadIdx.x;
    const int w    = tid >> 5;
    const int lane = tid & 31;
    const int lab64 = g_lab64;

    // --- Phase 1: deterministic match-queue build (ballot compaction) ---
    int cnt = 0;
    const int sstart = base + w * SUB;
#pragma unroll
    for (int k = 0; k < SUB / 32; k++) {
        int i = sstart + k * 32 + lane;
        bool pred = (i < N) && (load_label(labels_raw, i, lab64) == cls);
        unsigned mask = __ballot_sync(0xFFFFFFFFu, pred);
        if (pred) {
            int pos = cnt + __popc(mask & ((1u << lane) - 1u));
            queue[w * SUB + pos] = i;
        }
        cnt += __popc(mask);
    }
    if (lane == 0) wcount[w] = cnt;
    __syncthreads();

    const int c0 = wcount[0], c1 = wcount[1], c2 = wcount[2];
    const int p1 = c0, p2 = c0 + c1, p3 = p2 + c2;
    const int m  = p3 + wcount[3];

    // --- Phase 2: process matched anchors; all 3 variants per iteration ---
    float acc[8];
#pragma unroll
    for (int k = 0; k < 8; k++) acc[k] = 0.0f;
    double entW = 0.0;

#pragma unroll 1
    for (int e = w; e < m; e += NWRP) {
        int s, off;
        if (e < p1)      { s = 0; off = e; }
        else if (e < p2) { s = 1; off = e - p1; }
        else if (e < p3) { s = 2; off = e - p2; }
        else             { s = 3; off = e - p3; }
        const size_t ro = (size_t)queue[s * SUB + off] * DIM;

        const float4* ra = (const float4*)(a  + ro);
        const float4* rb = (const float4*)(b  + ro);
        const float4* rc = (const float4*)(cc + ro);

        // 6 independent 16B loads issued before any consumption.
        float4 a0 = ra[lane], a1 = ra[lane + 32];
        float4 b0 = rb[lane], b1 = rb[lane + 32];
        float4 c0v = rc[lane], c1v = rc[lane + 32];

        float as1, as2, asl, bs1, bs2, bsl, cs1, cs2, csl;
        lane_sums(a0, a1, as1, as2, asl);
        lane_sums(b0, b1, bs1, bs2, bsl);
        lane_sums(c0v, c1v, cs1, cs2, csl);

        accum_row(a0, a1, as1, as2, asl, acc, entW);
        accum_row(b0, b1, bs1, bs2, bsl, acc, entW);
        accum_row(c0v, c1v, cs1, cs2, csl, acc, entW);
    }

    // Rows processed by this warp: 3 per anchor, anchors e = w, w+4, ... < m.
    const int anchorsW = (m > w) ? ((m - w + NWRP - 1) / NWRP) : 0;

    // --- Phase 3: block reduce + single global flush ---
    if (m > 0) {
#pragma unroll
        for (int k = 0; k < 4; k++) {
            sred[w * DIM + 4 * lane + k]       = acc[k];
            sred[w * DIM + 128 + 4 * lane + k] = acc[4 + k];
        }
        if (lane == 0) { sent[w] = entW; swcnt[w] = 3 * anchorsW; }
        __syncthreads();

        // 128 threads, 256 dims -> 2 dims each
#pragma unroll
        for (int h = 0; h < 2; h++) {
            int d = tid + 128 * h;
            float sum = sred[0 * DIM + d] + sred[1 * DIM + d]
                      + sred[2 * DIM + d] + sred[3 * DIM + d];
            atomicAdd(&g_seg[cls * DIM + d], (double)sum);
        }
        if (tid == 0) {
            atomicAdd(&g_ent[cls], sent[0] + sent[1] + sent[2] + sent[3]);
            atomicAdd(&g_cnt[cls], swcnt[0] + swcnt[1] + swcnt[2] + swcnt[3]);
        }
    }
}

__global__ void finalize_kernel(float* out) {
    __shared__ double red[256];
    int t = threadIdx.x;
    double sum = 0.0;
    for (int idx = t; idx < CLS * DIM; idx += 256) {
        int c = idx >> 8;  // DIM == 256
        int n = g_cnt[c];
        if (n > 0) {
            double s   = g_seg[idx];
            double mix = s / (double)n;
            double lm  = log(fmax(mix, EPSF));
            sum -= s * lm / (double)n;
        }
    }
    if (t < CLS) {
        int n = g_cnt[t];
        if (n > 0) sum += g_ent[t] / (double)n;
    }
    red[t] = sum;
    __syncthreads();
    for (int s = 128; s > 0; s >>= 1) {
        if (t < s) red[t] += red[t + s];
        __syncthreads();
    }
    if (t == 0) out[0] = (float)(red[0] * (0.01 / (double)DIM));
}

extern "C" void kernel_launch(void* const* d_in, const int* in_sizes, int n_in,
                              void* d_out, int out_size)
{
    const float* a          = (const float*)d_in[0];
    const float* b          = (const float*)d_in[1];
    const float* c          = (const float*)d_in[2];
    const int*   labels_raw = (const int*)d_in[3];
    float* out = (float*)d_out;

    int N = in_sizes[0] / DIM;
    int nch = (N + CHUNK - 1) / CHUNK;

    zero_kernel<<<(CLS * DIM + 511) / 512, 512>>>(labels_raw, N);
    main_kernel<<<CLS * nch, NTHR>>>(a, b, c, labels_raw, N);
    finalize_kernel<<<1, 256>>>(out);
}

// round 15
// speedup vs baseline: 4.3361x; 4.3361x over previous
#include <cuda_runtime.h>
#include <cuda_bf16.h>

// SupJSD (ContrastiveLossPlus) — class-owned-block sufficient-statistics formulation.
//
// loss = 0.01/D * sum_c (1/n_c) * [ entsum_c - sum_d seg[c][d]*log(max(seg[c][d]/n_c, EPS)) ]
//   seg[c][d]  = sum over rows i (of 3N) with label c of p_i[d],  p_i = x_i / max(||x_i||_2, 1e-12)
//   entsum_c   = sum over rows i with label c of sum_d p_i[d]*ln(p_i[d])
//   n_c        = count over the 3N concatenated rows
// Per-row:  sum_d p ln p = inv*(S_xlogx + ln(inv)*S_x),  inv = 1/max(||x||,1e-12)
//
// R7 post-mortem: 348us came (by elimination) from 1.32M fp64 global atomics
// into 20480 addresses (64-deep collisions). This version has ZERO global
// atomics: every block writes its fp32 partials to a private scratch slot
// (plain STG), and a two-stage finalize reduces them in double. Deterministic.
//
// Labels may arrive as int32 or int64 (JAX x64 ambiguity): warp-parallel sniff
// sets g_lab64 (odd 32-bit words all zero -> int64).

#define CLS   80
#define DIM   256
#define EPSF  1e-7
#define CHUNK 1024
#define NTHR  128   // 4 warps
#define NWRP  4
#define SUB   (CHUNK / NWRP)   // 256 labels scanned per warp
#define MAXCH 96               // supports N up to 98304

__device__ float  g_pseg[MAXCH * CLS * DIM];  // [chunk][cls][dim] partials
__device__ double g_pent[MAXCH * CLS];
__device__ int    g_pcnt[MAXCH * CLS];
__device__ double g_cls[CLS];
__device__ int    g_lab64;

__global__ void sniff_kernel(const int* labels_raw, int N) {
    int lane = threadIdx.x;
    int samples = (N < 256) ? N : 256;
    int nz = 0;
    for (int k = lane; k < samples; k += 32) nz |= labels_raw[2 * k + 1];
#pragma unroll
    for (int off = 16; off > 0; off >>= 1)
        nz |= __shfl_xor_sync(0xFFFFFFFFu, nz, off);
    if (lane == 0) g_lab64 = (nz == 0) ? 1 : 0;
}

__device__ __forceinline__ int load_label(const int* labels_raw, int i, int lab64) {
    return lab64 ? (int)((const long long*)labels_raw)[i] : labels_raw[i];
}

// Per-lane partial sums for one row fragment (8 values in two float4s).
__device__ __forceinline__ void lane_sums(const float4& x0, const float4& x1,
                                          float& s1, float& s2, float& sl)
{
    float va[8] = {x0.x, x0.y, x0.z, x0.w, x1.x, x1.y, x1.z, x1.w};
    s1 = 0.f; s2 = 0.f; sl = 0.f;
#pragma unroll
    for (int k = 0; k < 8; k++) {
        float x = va[k];
        s1 += x;
        s2 = fmaf(x, x, s2);
        sl += (x > 0.f) ? x * __logf(x) : 0.f;
    }
}

__device__ __forceinline__ float warp_red(float v) {
#pragma unroll
    for (int off = 16; off > 0; off >>= 1)
        v += __shfl_xor_sync(0xFFFFFFFFu, v, off);
    return v;
}

__device__ __forceinline__ void accum_row(const float4& x0, const float4& x1,
                                          float s1, float s2, float sl,
                                          float acc[8], double& entW)
{
    s1 = warp_red(s1);
    s2 = warp_red(s2);
    sl = warp_red(sl);
    float inv = 1.0f / fmaxf(sqrtf(s2), 1e-12f);
    entW += (double)(inv * (sl + __logf(inv) * s1));
    acc[0] = fmaf(x0.x, inv, acc[0]);
    acc[1] = fmaf(x0.y, inv, acc[1]);
    acc[2] = fmaf(x0.z, inv, acc[2]);
    acc[3] = fmaf(x0.w, inv, acc[3]);
    acc[4] = fmaf(x1.x, inv, acc[4]);
    acc[5] = fmaf(x1.y, inv, acc[5]);
    acc[6] = fmaf(x1.z, inv, acc[6]);
    acc[7] = fmaf(x1.w, inv, acc[7]);
}

extern "C" __global__ void __launch_bounds__(NTHR, 8)
main_kernel(const float* __restrict__ a, const float* __restrict__ b,
            const float* __restrict__ cc, const int* __restrict__ labels_raw,
            int N)
{
    __shared__ int    queue[CHUNK];      // per-warp segments of SUB entries
    __shared__ int    wcount[NWRP];
    __shared__ float  sred[NWRP * DIM];  // 4 KB
    __shared__ double sent[NWRP];
    __shared__ int    swcnt[NWRP];

    const int cls  = blockIdx.x % CLS;
    const int jchk = blockIdx.x / CLS;
    const int base = jchk * CHUNK;

    const int tid  = threadIdx.x;
    const int w    = tid >> 5;
    const int lane = tid & 31;
    const int lab64 = g_lab64;

    // --- Phase 1: deterministic match-queue build (ballot compaction) ---
    int cnt = 0;
    const int sstart = base + w * SUB;
#pragma unroll
    for (int k = 0; k < SUB / 32; k++) {
        int i = sstart + k * 32 + lane;
        bool pred = (i < N) && (load_label(labels_raw, i, lab64) == cls);
        unsigned mask = __ballot_sync(0xFFFFFFFFu, pred);
        if (pred) {
            int pos = cnt + __popc(mask & ((1u << lane) - 1u));
            queue[w * SUB + pos] = i;
        }
        cnt += __popc(mask);
    }
    if (lane == 0) wcount[w] = cnt;
    __syncthreads();

    const int c0 = wcount[0], c1 = wcount[1], c2 = wcount[2];
    const int p1 = c0, p2 = c0 + c1, p3 = p2 + c2;
    const int m  = p3 + wcount[3];

    // --- Phase 2: process matched anchors; all 3 variants per iteration ---
    float acc[8];
#pragma unroll
    for (int k = 0; k < 8; k++) acc[k] = 0.0f;
    double entW = 0.0;

#pragma unroll 1
    for (int e = w; e < m; e += NWRP) {
        int s, off;
        if (e < p1)      { s = 0; off = e; }
        else if (e < p2) { s = 1; off = e - p1; }
        else if (e < p3) { s = 2; off = e - p2; }
        else             { s = 3; off = e - p3; }
        const size_t ro = (size_t)queue[s * SUB + off] * DIM;

        const float4* ra = (const float4*)(a  + ro);
        const float4* rb = (const float4*)(b  + ro);
        const float4* rc = (const float4*)(cc + ro);

        // 6 independent 16B loads issued before any consumption.
        float4 a0 = ra[lane], a1 = ra[lane + 32];
        float4 b0 = rb[lane], b1 = rb[lane + 32];
        float4 c0v = rc[lane], c1v = rc[lane + 32];

        float as1, as2, asl, bs1, bs2, bsl, cs1, cs2, csl;
        lane_sums(a0, a1, as1, as2, asl);
        lane_sums(b0, b1, bs1, bs2, bsl);
        lane_sums(c0v, c1v, cs1, cs2, csl);

        accum_row(a0, a1, as1, as2, asl, acc, entW);
        accum_row(b0, b1, bs1, bs2, bsl, acc, entW);
        accum_row(c0v, c1v, cs1, cs2, csl, acc, entW);
    }

    // Rows processed by this warp: 3 per anchor, anchors e = w, w+4, ... < m.
    const int anchorsW = (m > w) ? ((m - w + NWRP - 1) / NWRP) : 0;

    // --- Phase 3: block reduce + plain STG flush to this block's slot ---
#pragma unroll
    for (int k = 0; k < 4; k++) {
        sred[w * DIM + 4 * lane + k]       = acc[k];
        sred[w * DIM + 128 + 4 * lane + k] = acc[4 + k];
    }
    if (lane == 0) { sent[w] = entW; swcnt[w] = 3 * anchorsW; }
    __syncthreads();

    // blockIdx.x == jchk*CLS + cls, used directly as the scratch slot.
#pragma unroll
    for (int h = 0; h < 2; h++) {
        int d = tid + 128 * h;
        float sum = sred[0 * DIM + d] + sred[1 * DIM + d]
                  + sred[2 * DIM + d] + sred[3 * DIM + d];
        g_pseg[(size_t)blockIdx.x * DIM + d] = sum;
    }
    if (tid == 0) {
        g_pent[blockIdx.x] = sent[0] + sent[1] + sent[2] + sent[3];
        g_pcnt[blockIdx.x] = swcnt[0] + swcnt[1] + swcnt[2] + swcnt[3];
    }
}

// One block per class: reduce chunk partials (double accumulation), compute
// the per-class bracket, write g_cls[c]. Deterministic order.
__global__ void finalize1_kernel(int nch) {
    __shared__ double sb[DIM];
    __shared__ int    sc[DIM];
    const int c = blockIdx.x;
    const int t = threadIdx.x;

    // Reduce ent and cnt over chunks.
    double entp = 0.0; int cntp = 0;
    for (int ch = t; ch < nch; ch += DIM) {
        entp += g_pent[ch * CLS + c];
        cntp += g_pcnt[ch * CLS + c];
    }
    sb[t] = entp; sc[t] = cntp;
    __syncthreads();
    for (int s = DIM / 2; s > 0; s >>= 1) {
        if (t < s) { sb[t] += sb[t + s]; sc[t] += sc[t + s]; }
        __syncthreads();
    }
    const double entsum = sb[0];
    const int    n      = sc[0];
    __syncthreads();

    // Per-dim segment sum over chunks (coalesced across t), then bracket term.
    double term = 0.0;
    if (n > 0) {
        double segd = 0.0;
        for (int ch = 0; ch < nch; ch++)
            segd += (double)g_pseg[((size_t)ch * CLS + c) * DIM + t];
        double mix = segd / (double)n;
        double lm  = log(fmax(mix, EPSF));
        term = -segd * lm / (double)n;
    }
    sb[t] = term;
    __syncthreads();
    for (int s = DIM / 2; s > 0; s >>= 1) {
        if (t < s) sb[t] += sb[t + s];
        __syncthreads();
    }
    if (t == 0)
        g_cls[c] = (n > 0) ? (sb[0] + entsum / (double)n) : 0.0;
}

__global__ void finalize2_kernel(float* out) {
    __shared__ double red[128];
    int t = threadIdx.x;
    double sum = (t < CLS) ? g_cls[t] : 0.0;
    red[t] = sum;
    __syncthreads();
    for (int s = 64; s > 0; s >>= 1) {
        if (t < s) red[t] += red[t + s];
        __syncthreads();
    }
    if (t == 0) out[0] = (float)(red[0] * (0.01 / (double)DIM));
}

extern "C" void kernel_launch(void* const* d_in, const int* in_sizes, int n_in,
                              void* d_out, int out_size)
{
    const float* a          = (const float*)d_in[0];
    const float* b          = (const float*)d_in[1];
    const float* c          = (const float*)d_in[2];
    const int*   labels_raw = (const int*)d_in[3];
    float* out = (float*)d_out;

    int N = in_sizes[0] / DIM;
    int nch = (N + CHUNK - 1) / CHUNK;
    if (nch > MAXCH) nch = MAXCH;   // N fixed at 65536 for this problem (nch=64)

    sniff_kernel<<<1, 32>>>(labels_raw, N);
    main_kernel<<<CLS * nch, NTHR>>>(a, b, c, labels_raw, N);
    finalize1_kernel<<<CLS, DIM>>>(nch);
    finalize2_kernel<<<1, 128>>>(out);
}

// round 17
// speedup vs baseline: 4.3903x; 1.0125x over previous
#include <cuda_runtime.h>
#include <cuda_bf16.h>

// SupJSD (ContrastiveLossPlus) — class-owned-block sufficient-statistics formulation.
//
// loss = 0.01/D * sum_c (1/n_c) * [ entsum_c - sum_d seg[c][d]*log(max(seg[c][d]/n_c, EPS)) ]
// R7->R15: removing the fp64 global-atomic flush took 348us -> 80.4us (theory
// confirmed). R16: fold the two tiny kernels' launch overhead (~7-9us total):
//   - label-dtype sniff moved into main_kernel (per-block, 32 samples, ballot)
//   - finalize1+finalize2 fused via last-block-done ticket (deterministic)
// Hot loop unchanged.

#define CLS   80
#define DIM   256
#define EPSF  1e-7
#define CHUNK 1024
#define NTHR  128   // 4 warps
#define NWRP  4
#define SUB   (CHUNK / NWRP)   // 256 labels scanned per warp
#define MAXCH 96               // supports N up to 98304

__device__ float  g_pseg[MAXCH * CLS * DIM];  // [chunk][cls][dim] partials
__device__ double g_pent[MAXCH * CLS];
__device__ int    g_pcnt[MAXCH * CLS];
__device__ double g_cls[CLS];
__device__ int    g_done;                      // zero-init; self-resetting

__device__ __forceinline__ int load_label(const int* labels_raw, int i, int lab64) {
    return lab64 ? (int)((const long long*)labels_raw)[i] : labels_raw[i];
}

// Per-lane partial sums for one row fragment (8 values in two float4s).
__device__ __forceinline__ void lane_sums(const float4& x0, const float4& x1,
                                          float& s1, float& s2, float& sl)
{
    float va[8] = {x0.x, x0.y, x0.z, x0.w, x1.x, x1.y, x1.z, x1.w};
    s1 = 0.f; s2 = 0.f; sl = 0.f;
#pragma unroll
    for (int k = 0; k < 8; k++) {
        float x = va[k];
        s1 += x;
        s2 = fmaf(x, x, s2);
        sl += (x > 0.f) ? x * __logf(x) : 0.f;
    }
}

__device__ __forceinline__ float warp_red(float v) {
#pragma unroll
    for (int off = 16; off > 0; off >>= 1)
        v += __shfl_xor_sync(0xFFFFFFFFu, v, off);
    return v;
}

__device__ __forceinline__ void accum_row(const float4& x0, const float4& x1,
                                          float s1, float s2, float sl,
                                          float acc[8], double& entW)
{
    s1 = warp_red(s1);
    s2 = warp_red(s2);
    sl = warp_red(sl);
    float inv = 1.0f / fmaxf(sqrtf(s2), 1e-12f);
    entW += (double)(inv * (sl + __logf(inv) * s1));
    acc[0] = fmaf(x0.x, inv, acc[0]);
    acc[1] = fmaf(x0.y, inv, acc[1]);
    acc[2] = fmaf(x0.z, inv, acc[2]);
    acc[3] = fmaf(x0.w, inv, acc[3]);
    acc[4] = fmaf(x1.x, inv, acc[4]);
    acc[5] = fmaf(x1.y, inv, acc[5]);
    acc[6] = fmaf(x1.z, inv, acc[6]);
    acc[7] = fmaf(x1.w, inv, acc[7]);
}

extern "C" __global__ void __launch_bounds__(NTHR, 8)
main_kernel(const float* __restrict__ a, const float* __restrict__ b,
            const float* __restrict__ cc, const int* __restrict__ labels_raw,
            int N)
{
    __shared__ int    queue[CHUNK];      // per-warp segments of SUB entries
    __shared__ int    wcount[NWRP];
    __shared__ float  sred[NWRP * DIM];  // 4 KB
    __shared__ double sent[NWRP];
    __shared__ int    swcnt[NWRP];
    __shared__ int    s_lab64;

    const int cls  = blockIdx.x % CLS;
    const int jchk = blockIdx.x / CLS;
    const int base = jchk * CHUNK;

    const int tid  = threadIdx.x;
    const int w    = tid >> 5;
    const int lane = tid & 31;

    // --- Phase 0: per-block label-dtype sniff (int64 LE labels in [0,80):
    // every odd 32-bit word is 0; 32 samples -> P(false positive) ~ 80^-32).
    if (tid < 32) {
        int v = (tid < N) ? labels_raw[2 * tid + 1] : 0;
        unsigned nzmask = __ballot_sync(0xFFFFFFFFu, v != 0);
        if (tid == 0) s_lab64 = (nzmask == 0) ? 1 : 0;
    }
    __syncthreads();
    const int lab64 = s_lab64;

    // --- Phase 1: deterministic match-queue build (ballot compaction) ---
    int cnt = 0;
    const int sstart = base + w * SUB;
#pragma unroll
    for (int k = 0; k < SUB / 32; k++) {
        int i = sstart + k * 32 + lane;
        bool pred = (i < N) && (load_label(labels_raw, i, lab64) == cls);
        unsigned mask = __ballot_sync(0xFFFFFFFFu, pred);
        if (pred) {
            int pos = cnt + __popc(mask & ((1u << lane) - 1u));
            queue[w * SUB + pos] = i;
        }
        cnt += __popc(mask);
    }
    if (lane == 0) wcount[w] = cnt;
    __syncthreads();

    const int c0 = wcount[0], c1 = wcount[1], c2 = wcount[2];
    const int p1 = c0, p2 = c0 + c1, p3 = p2 + c2;
    const int m  = p3 + wcount[3];

    // --- Phase 2: process matched anchors; all 3 variants per iteration ---
    float acc[8];
#pragma unroll
    for (int k = 0; k < 8; k++) acc[k] = 0.0f;
    double entW = 0.0;

#pragma unroll 1
    for (int e = w; e < m; e += NWRP) {
        int s, off;
        if (e < p1)      { s = 0; off = e; }
        else if (e < p2) { s = 1; off = e - p1; }
        else if (e < p3) { s = 2; off = e - p2; }
        else             { s = 3; off = e - p3; }
        const size_t ro = (size_t)queue[s * SUB + off] * DIM;

        const float4* ra = (const float4*)(a  + ro);
        const float4* rb = (const float4*)(b  + ro);
        const float4* rc = (const float4*)(cc + ro);

        // 6 independent 16B loads issued before any consumption.
        float4 a0 = ra[lane], a1 = ra[lane + 32];
        float4 b0 = rb[lane], b1 = rb[lane + 32];
        float4 c0v = rc[lane], c1v = rc[lane + 32];

        float as1, as2, asl, bs1, bs2, bsl, cs1, cs2, csl;
        lane_sums(a0, a1, as1, as2, asl);
        lane_sums(b0, b1, bs1, bs2, bsl);
        lane_sums(c0v, c1v, cs1, cs2, csl);

        accum_row(a0, a1, as1, as2, asl, acc, entW);
        accum_row(b0, b1, bs1, bs2, bsl, acc, entW);
        accum_row(c0v, c1v, cs1, cs2, csl, acc, entW);
    }

    // Rows processed by this warp: 3 per anchor, anchors e = w, w+4, ... < m.
    const int anchorsW = (m > w) ? ((m - w + NWRP - 1) / NWRP) : 0;

    // --- Phase 3: block reduce + plain STG flush to this block's slot ---
#pragma unroll
    for (int k = 0; k < 4; k++) {
        sred[w * DIM + 4 * lane + k]       = acc[k];
        sred[w * DIM + 128 + 4 * lane + k] = acc[4 + k];
    }
    if (lane == 0) { sent[w] = entW; swcnt[w] = 3 * anchorsW; }
    __syncthreads();

    // blockIdx.x == jchk*CLS + cls, used directly as the scratch slot.
#pragma unroll
    for (int h = 0; h < 2; h++) {
        int d = tid + 128 * h;
        float sum = sred[0 * DIM + d] + sred[1 * DIM + d]
                  + sred[2 * DIM + d] + sred[3 * DIM + d];
        g_pseg[(size_t)blockIdx.x * DIM + d] = sum;
    }
    if (tid == 0) {
        g_pent[blockIdx.x] = sent[0] + sent[1] + sent[2] + sent[3];
        g_pcnt[blockIdx.x] = swcnt[0] + swcnt[1] + swcnt[2] + swcnt[3];
    }
}

// One block per class: reduce chunk partials (double accumulation), compute
// the per-class bracket, write g_cls[c]. The LAST block to finish (ticket
// counter) then sums the 80 class values in fixed order and writes out[0].
__global__ void finalize_kernel(float* out, int nch) {
    __shared__ double sb[DIM];
    __shared__ int    sc[DIM];
    __shared__ int    ticket;
    const int c = blockIdx.x;
    const int t = threadIdx.x;

    // Reduce ent and cnt over chunks.
    double entp = 0.0; int cntp = 0;
    for (int ch = t; ch < nch; ch += DIM) {
        entp += g_pent[ch * CLS + c];
        cntp += g_pcnt[ch * CLS + c];
    }
    sb[t] = entp; sc[t] = cntp;
    __syncthreads();
    for (int s = DIM / 2; s > 0; s >>= 1) {
        if (t < s) { sb[t] += sb[t + s]; sc[t] += sc[t + s]; }
        __syncthreads();
    }
    const double entsum = sb[0];
    const int    n      = sc[0];
    __syncthreads();

    // Per-dim segment sum over chunks (coalesced across t), then bracket term.
    double term = 0.0;
    if (n > 0) {
        double segd = 0.0;
        for (int ch = 0; ch < nch; ch++)
            segd += (double)g_pseg[((size_t)ch * CLS + c) * DIM + t];
        double mix = segd / (double)n;
        double lm  = log(fmax(mix, EPSF));
        term = -segd * lm / (double)n;
    }
    sb[t] = term;
    __syncthreads();
    for (int s = DIM / 2; s > 0; s >>= 1) {
        if (t < s) sb[t] += sb[t + s];
        __syncthreads();
    }
    if (t == 0) {
        g_cls[c] = (n > 0) ? (sb[0] + entsum / (double)n) : 0.0;
        __threadfence();
        ticket = atomicAdd(&g_done, 1);
    }
    __syncthreads();

    // Last block: fixed-order (deterministic) sum of the 80 class values.
    if (ticket == CLS - 1) {
        double v = 0.0;
        if (t < CLS) v = ((volatile double*)g_cls)[t];
        sb[t] = v;
        __syncthreads();
        for (int s = DIM / 2; s > 0; s >>= 1) {
            if (t < s) sb[t] += sb[t + s];
            __syncthreads();
        }
        if (t == 0) {
            out[0] = (float)(sb[0] * (0.01 / (double)DIM));
            g_done = 0;   // reset for next graph replay
        }
    }
}

extern "C" void kernel_launch(void* const* d_in, const int* in_sizes, int n_in,
                              void* d_out, int out_size)
{
    const float* a          = (const float*)d_in[0];
    const float* b          = (const float*)d_in[1];
    const float* c          = (const float*)d_in[2];
    const int*   labels_raw = (const int*)d_in[3];
    float* out = (float*)d_out;

    int N = in_sizes[0] / DIM;
    int nch = (N + CHUNK - 1) / CHUNK;
    if (nch > MAXCH) nch = MAXCH;   // N fixed at 65536 for this problem (nch=64)

    main_kernel<<<CLS * nch, NTHR>>>(a, b, c, labels_raw, N);
    finalize_kernel<<<CLS, DIM>>>(out, nch);
}